// round 2
// baseline (speedup 1.0000x reference)
#include <cuda_runtime.h>
#include <cuda_bf16.h>
#include <cstdint>

// Problem constants
#define NUM_FIELDS 16
#define EMBED      256
#define BATCH      2048
#define NUM_PAIRS  120

// Tiling
#define BM 128
#define BN 128
#define BK 16
#define THREADS 256

#define A_STRIDE (BK + 4)   // 20 floats -> conflict-free fragment loads
#define B_STRIDE (BN + 4)   // 132 floats

__device__ __forceinline__ uint32_t smem_u32(const void* p) {
    return (uint32_t)__cvta_generic_to_shared(p);
}

__device__ __forceinline__ void cp_async16(uint32_t dst, const void* src) {
    asm volatile("cp.async.cg.shared.global [%0], [%1], 16;\n" :: "r"(dst), "l"(src));
}

__device__ __forceinline__ void cp_commit() {
    asm volatile("cp.async.commit_group;\n" ::: "memory");
}

__device__ __forceinline__ uint32_t f2tf32(float f) {
    uint32_t r;
    asm("cvt.rna.tf32.f32 %0, %1;" : "=r"(r) : "f"(f));
    return r;
}

__device__ __forceinline__ void mma_tf32(float c[4], const uint32_t a[4], const uint32_t b[2]) {
    asm volatile(
        "mma.sync.aligned.m16n8k8.row.col.f32.tf32.tf32.f32 "
        "{%0,%1,%2,%3}, {%4,%5,%6,%7}, {%8,%9}, {%0,%1,%2,%3};\n"
        : "+f"(c[0]), "+f"(c[1]), "+f"(c[2]), "+f"(c[3])
        : "r"(a[0]), "r"(a[1]), "r"(a[2]), "r"(a[3]), "r"(b[0]), "r"(b[1]));
}

__global__ void __launch_bounds__(THREADS, 2)
bilinear_kernel(const float* __restrict__ emb,
                const float* __restrict__ weight,
                const float* __restrict__ bias,
                float* __restrict__ out)
{
    const int p   = blockIdx.z;
    const int bm0 = blockIdx.x * BM;
    const int bn0 = blockIdx.y * BN;

    // pair p -> (i, j) of triu_indices(16, k=1)
    int i = 0, rem = p;
    while (rem >= (NUM_FIELDS - 1) - i) { rem -= (NUM_FIELDS - 1) - i; ++i; }
    const int j = i + 1 + rem;

    __shared__ float As[2][BM][A_STRIDE];
    __shared__ float Bs[2][BK][B_STRIDE];

    const int tid  = threadIdx.x;
    const int lane = tid & 31;
    const int warp = tid >> 5;
    const int wm   = warp & 1;    // 0..1  (64-row slab)
    const int wn   = warp >> 1;   // 0..3  (32-col slab)
    const int g    = lane >> 2;   // 0..7
    const int t4   = lane & 3;    // 0..3

    const float* Aglob = emb + (size_t)bm0 * (NUM_FIELDS * EMBED) + i * EMBED;
    const float* Bglob = weight + (size_t)p * (EMBED * EMBED) + bn0;

    float acc[4][4][4];
    #pragma unroll
    for (int mi = 0; mi < 4; ++mi)
        #pragma unroll
        for (int ni = 0; ni < 4; ++ni)
            #pragma unroll
            for (int r = 0; r < 4; ++r)
                acc[mi][ni][r] = 0.0f;

    // ---- async tile loaders -------------------------------------------------
    // A tile: BM(128) rows x BK(16) floats = 512 float4, 2 per thread
    // B tile: BK(16)  rows x BN(128) floats = 512 float4, 2 per thread
    auto load_tiles = [&](int buf, int k0) {
        #pragma unroll
        for (int it = 0; it < 2; ++it) {
            int idx = tid + it * THREADS;
            int m   = idx >> 2;          // 0..127
            int kq  = idx & 3;           // float4 in k
            cp_async16(smem_u32(&As[buf][m][kq * 4]),
                       Aglob + (size_t)m * (NUM_FIELDS * EMBED) + k0 + kq * 4);
        }
        #pragma unroll
        for (int it = 0; it < 2; ++it) {
            int idx = tid + it * THREADS;
            int kr  = idx >> 5;          // 0..15
            int nq  = idx & 31;          // float4 in n
            cp_async16(smem_u32(&Bs[buf][kr][nq * 4]),
                       Bglob + (size_t)(k0 + kr) * EMBED + nq * 4);
        }
    };

    const int NK = EMBED / BK;   // 16

    load_tiles(0, 0);
    cp_commit();

    for (int kt = 0; kt < NK; ++kt) {
        if (kt + 1 < NK) {
            load_tiles((kt + 1) & 1, (kt + 1) * BK);
            cp_commit();
            asm volatile("cp.async.wait_group 1;\n" ::: "memory");
        } else {
            asm volatile("cp.async.wait_group 0;\n" ::: "memory");
        }
        __syncthreads();

        const int buf = kt & 1;

        #pragma unroll
        for (int ks = 0; ks < BK / 8; ++ks) {
            uint32_t afrag[4][4];
            #pragma unroll
            for (int mi = 0; mi < 4; ++mi) {
                const int rm = wm * 64 + mi * 16;
                afrag[mi][0] = f2tf32(As[buf][rm + g    ][ks * 8 + t4    ]);
                afrag[mi][1] = f2tf32(As[buf][rm + g + 8][ks * 8 + t4    ]);
                afrag[mi][2] = f2tf32(As[buf][rm + g    ][ks * 8 + t4 + 4]);
                afrag[mi][3] = f2tf32(As[buf][rm + g + 8][ks * 8 + t4 + 4]);
            }
            uint32_t bfrag[4][2];
            #pragma unroll
            for (int ni = 0; ni < 4; ++ni) {
                const int cn = wn * 32 + ni * 8 + g;
                bfrag[ni][0] = f2tf32(Bs[buf][ks * 8 + t4    ][cn]);
                bfrag[ni][1] = f2tf32(Bs[buf][ks * 8 + t4 + 4][cn]);
            }
            #pragma unroll
            for (int mi = 0; mi < 4; ++mi)
                #pragma unroll
                for (int ni = 0; ni < 4; ++ni)
                    mma_tf32(acc[mi][ni], afrag[mi], bfrag[ni]);
        }
        __syncthreads();
    }

    // ---- epilogue: out[b,p,f] = acc * emb[b,j,f] + bias[p,f] ---------------
    const float* biasP = bias + (size_t)p * EMBED;

    #pragma unroll
    for (int mi = 0; mi < 4; ++mi) {
        const int r0 = bm0 + wm * 64 + mi * 16 + g;
        #pragma unroll
        for (int ni = 0; ni < 4; ++ni) {
            const int c = bn0 + wn * 32 + ni * 8 + t4 * 2;
            const float2 bb = *(const float2*)(biasP + c);
            #pragma unroll
            for (int h = 0; h < 2; ++h) {
                const int row = r0 + h * 8;
                const float2 q = *(const float2*)(emb + (size_t)row * (NUM_FIELDS * EMBED)
                                                   + j * EMBED + c);
                float2 v;
                v.x = acc[mi][ni][h * 2 + 0] * q.x + bb.x;
                v.y = acc[mi][ni][h * 2 + 1] * q.y + bb.y;
                *(float2*)(out + (size_t)row * (NUM_PAIRS * EMBED) + (size_t)p * EMBED + c) = v;
            }
        }
    }
}

extern "C" void kernel_launch(void* const* d_in, const int* in_sizes, int n_in,
                              void* d_out, int out_size) {
    const float* emb    = (const float*)d_in[0];
    const float* weight = (const float*)d_in[1];
    const float* bias   = (const float*)d_in[2];
    float* out          = (float*)d_out;

    dim3 grid(BATCH / BM, EMBED / BN, NUM_PAIRS);
    dim3 block(THREADS);
    bilinear_kernel<<<grid, block>>>(emb, weight, bias, out);
}